// round 6
// baseline (speedup 1.0000x reference)
#include <cuda_runtime.h>
#include <math.h>

// Scratch for per-node projections: P[n][0:16] = z[n] @ W1[0:128,:],
// P[n][16:32] = z[n] @ W1[128:256,:].  Sized for N up to 131072 (actual N=100000).
#define MAX_NODES (131072)
__device__ __align__(16) float g_P[(size_t)MAX_NODES * 32];

// Flag: 1 if edge_index is stored as int64 on device, 0 if int32.
__device__ int g_ei_is64;

// ---------------------------------------------------------------------------
// Packed fp32x2 helpers (FFMA2 — only reachable via PTX fma.rn.f32x2)
// ---------------------------------------------------------------------------
__device__ __forceinline__ void ffma2(unsigned long long& d,
                                      unsigned long long a,
                                      unsigned long long b)
{
    asm("fma.rn.f32x2 %0, %1, %2, %0;" : "+l"(d) : "l"(a), "l"(b));
}
__device__ __forceinline__ unsigned long long pk2(float v)
{
    unsigned long long r;
    asm("mov.b64 %0, {%1, %1};" : "=l"(r) : "f"(v));
    return r;
}

// ---------------------------------------------------------------------------
// Kernel 0: detect edge_index storage dtype (parallel, one DRAM round trip).
// If the buffer is int32, an int64 read landing in [0,N) requires the paired
// high word to be exactly 0 (p ~ 2e-5 per entry); 32 consecutive hits is
// impossible. All reads stay within the first 256 bytes, owned by either
// layout (int32 buffer is 8E bytes total).
// ---------------------------------------------------------------------------
__global__ void detect_kernel(const long long* __restrict__ ei, int E, int N)
{
    int i = threadIdx.x;
    int cnt = E < 32 ? E : 32;
    bool ok = true;
    if (i < cnt) {
        long long v = ei[i];
        ok = (v >= 0 && v < (long long)N);
    }
    unsigned m = __ballot_sync(0xffffffffu, ok);
    if (i == 0) g_ei_is64 = (m == 0xffffffffu) ? 1 : 0;
}

// ---------------------------------------------------------------------------
// Kernel 1: per-node projection.  One thread per node, W1 staged in smem,
// accumulation in packed fp32x2 (halves fma-pipe instruction count).
// ---------------------------------------------------------------------------
__global__ __launch_bounds__(256)
void proj_kernel(const float* __restrict__ z,
                 const float* __restrict__ W1,   // [256,16] row-major
                 int N)
{
    __shared__ __align__(16) float sW1[256 * 16];
    for (int i = threadIdx.x; i < 256 * 16; i += blockDim.x)
        sW1[i] = W1[i];
    __syncthreads();

    int n = blockIdx.x * blockDim.x + threadIdx.x;
    if (n >= N) return;

    const float4* z4 = reinterpret_cast<const float4*>(z) + (size_t)n * 32;

    // 16 packed accumulators = 32 fp32 lanes (accT pairs 0..7, accB pairs 0..7)
    unsigned long long accT2[8], accB2[8];
#pragma unroll
    for (int j = 0; j < 8; j++) { accT2[j] = 0ull; accB2[j] = 0ull; }

#pragma unroll 4
    for (int i = 0; i < 32; i++) {
        float4 zz = z4[i];
        float zv[4] = { zz.x, zz.y, zz.z, zz.w };
#pragma unroll
        for (int k = 0; k < 4; k++) {
            int d = i * 4 + k;
            unsigned long long zp = pk2(zv[k]);
            const ulonglong2* wt = reinterpret_cast<const ulonglong2*>(&sW1[d * 16]);
            const ulonglong2* wb = reinterpret_cast<const ulonglong2*>(&sW1[(128 + d) * 16]);
#pragma unroll
            for (int q = 0; q < 4; q++) {
                ulonglong2 pt = wt[q];
                ulonglong2 pb = wb[q];
                ffma2(accT2[q * 2 + 0], zp, pt.x);
                ffma2(accT2[q * 2 + 1], zp, pt.y);
                ffma2(accB2[q * 2 + 0], zp, pb.x);
                ffma2(accB2[q * 2 + 1], zp, pb.y);
            }
        }
    }

    // P layout per node: [T0..T15, B0..B15]; packed pairs are already in order.
    ulonglong2* P2 = reinterpret_cast<ulonglong2*>(g_P) + (size_t)n * 8;
#pragma unroll
    for (int q = 0; q < 4; q++) {
        ulonglong2 t; t.x = accT2[q * 2]; t.y = accT2[q * 2 + 1];
        ulonglong2 b; b.x = accB2[q * 2]; b.y = accB2[q * 2 + 1];
        P2[q]     = t;
        P2[4 + q] = b;
    }
}

// ---------------------------------------------------------------------------
// Kernel 2: per-edge work.  4 lanes per edge (lanes contiguous in a warp).
//   - adj_logits = dot(z[row], z[col])          (128 fp32 MACs, split 4 ways)
//   - h = relu(P_top[row] + P_bot[col] + b1)    (16 units, 4 per lane)
//   - weights = softplus(h @ W2 + b2)
// out layout: [adj_logits (E), weights (E)]
// ---------------------------------------------------------------------------
__global__ __launch_bounds__(256)
void edge_kernel(const float* __restrict__ z,
                 const void* __restrict__ ei_raw,   // [2,E] int64 OR int32
                 const float* __restrict__ b1,
                 const float* __restrict__ W2,
                 const float* __restrict__ b2,
                 float* __restrict__ out,
                 int E, int N)
{
    int t   = blockIdx.x * blockDim.x + threadIdx.x;
    int e   = t >> 2;
    int sub = t & 3;
    bool valid = (e < E);
    int ec = valid ? e : (E - 1);   // clamp so all lanes stay active for shuffles

    int row, col;
    if (g_ei_is64) {
        const long long* ei = (const long long*)ei_raw;
        row = (int)ei[ec];
        col = (int)ei[(size_t)E + ec];
    } else {
        const int* ei = (const int*)ei_raw;
        row = ei[ec];
        col = ei[(size_t)E + ec];
    }
    // final safety clamp (branchless; indices should already be in range)
    row = min(max(row, 0), N - 1);
    col = min(max(col, 0), N - 1);

    const float4* zr = reinterpret_cast<const float4*>(z) + (size_t)row * 32;
    const float4* zc = reinterpret_cast<const float4*>(z) + (size_t)col * 32;

    float acc = 0.f;
#pragma unroll
    for (int i = 0; i < 8; i++) {
        float4 a = zr[sub + 4 * i];
        float4 b = zc[sub + 4 * i];
        acc = fmaf(a.x, b.x, acc);
        acc = fmaf(a.y, b.y, acc);
        acc = fmaf(a.z, b.z, acc);
        acc = fmaf(a.w, b.w, acc);
    }
    acc += __shfl_xor_sync(0xffffffffu, acc, 1);
    acc += __shfl_xor_sync(0xffffffffu, acc, 2);

    // MLP: each lane covers 4 hidden units
    const float4* P4 = reinterpret_cast<const float4*>(g_P);
    float4 pr = P4[(size_t)row * 8 + sub];        // top part of P[row]
    float4 pc = P4[(size_t)col * 8 + 4 + sub];    // bottom part of P[col]
    float4 bb = reinterpret_cast<const float4*>(b1)[sub];
    float4 w2 = reinterpret_cast<const float4*>(W2)[sub];

    float h0 = fmaxf(pr.x + pc.x + bb.x, 0.f);
    float h1 = fmaxf(pr.y + pc.y + bb.y, 0.f);
    float h2 = fmaxf(pr.z + pc.z + bb.z, 0.f);
    float h3 = fmaxf(pr.w + pc.w + bb.w, 0.f);

    float part = h0 * w2.x + h1 * w2.y + h2 * w2.z + h3 * w2.w;
    part += __shfl_xor_sync(0xffffffffu, part, 1);
    part += __shfl_xor_sync(0xffffffffu, part, 2);

    if (valid && sub == 0) {
        float x = part + b2[0];
        // numerically stable softplus, matches jax.nn.softplus
        float w = fmaxf(x, 0.f) + log1pf(expf(-fabsf(x)));
        out[e]             = acc;
        out[(size_t)E + e] = w;
    }
}

// ---------------------------------------------------------------------------
// Launch
// ---------------------------------------------------------------------------
extern "C" void kernel_launch(void* const* d_in, const int* in_sizes, int n_in,
                              void* d_out, int out_size)
{
    const float* z  = (const float*)d_in[0];        // [N,128] f32
    const void*  ei = d_in[1];                      // [2,E]   i64 or i32
    const float* W1 = (const float*)d_in[2];        // [256,16] f32
    const float* b1 = (const float*)d_in[3];        // [16]
    const float* W2 = (const float*)d_in[4];        // [16,1]
    const float* b2 = (const float*)d_in[5];        // [1]
    float*       out = (float*)d_out;

    int N = in_sizes[0] / 128;
    int E = in_sizes[1] / 2;

    detect_kernel<<<1, 32>>>((const long long*)ei, E, N);

    int blocks1 = (N + 255) / 256;
    proj_kernel<<<blocks1, 256>>>(z, W1, N);

    long long threads2 = (long long)E * 4;
    int blocks2 = (int)((threads2 + 255) / 256);
    edge_kernel<<<blocks2, 256>>>(z, ei, b1, W2, b2, out, E, N);
}

// round 7
// speedup vs baseline: 1.0893x; 1.0893x over previous
#include <cuda_runtime.h>
#include <cuda_fp16.h>
#include <math.h>

// Scratch: per-node projections P[n][0:16] = z[n]@W1_top, P[n][16:32] = z[n]@W1_bot.
// Plus an fp16 shadow copy of z for the adj_logits dot (halves gather traffic).
// Sized for N up to 131072 (actual N=100000).
#define MAX_NODES (131072)
__device__ __align__(16) float  g_P [(size_t)MAX_NODES * 32];
__device__ __align__(16) __half g_zh[(size_t)MAX_NODES * 128];

// Flag: 1 if edge_index is stored as int64 on device, 0 if int32.
__device__ int g_ei_is64;

// ---------------------------------------------------------------------------
// Kernel 1: per-node projection + fp16 z shadow copy + edge-dtype detect.
// One thread per node; W1 staged in smem (broadcast reads, conflict-free).
// Detection folded into block 0 warp 0: if the buffer were int32, an int64
// read landing in [0,N) needs its high word == 0 (p ~ 2e-5); 32 consecutive
// hits is impossible. Reads stay within the first 256 bytes of either layout.
// ---------------------------------------------------------------------------
__global__ __launch_bounds__(256)
void proj_kernel(const float* __restrict__ z,
                 const float* __restrict__ W1,   // [256,16] row-major
                 const long long* __restrict__ ei_as64,
                 int N, int E)
{
    __shared__ __align__(16) float sW1[256 * 16];
    for (int i = threadIdx.x; i < 256 * 16; i += blockDim.x)
        sW1[i] = W1[i];

    if (blockIdx.x == 0 && threadIdx.x < 32) {
        int cnt = E < 32 ? E : 32;
        bool ok = true;
        if (threadIdx.x < cnt) {
            long long v = ei_as64[threadIdx.x];
            ok = (v >= 0 && v < (long long)N);
        }
        unsigned m = __ballot_sync(0xffffffffu, ok);
        if (threadIdx.x == 0) g_ei_is64 = (m == 0xffffffffu) ? 1 : 0;
    }
    __syncthreads();

    int n = blockIdx.x * blockDim.x + threadIdx.x;
    if (n >= N) return;

    const float4* z4 = reinterpret_cast<const float4*>(z) + (size_t)n * 32;
    uint2* zh2 = reinterpret_cast<uint2*>(g_zh) + (size_t)n * 32;

    float accT[16], accB[16];
#pragma unroll
    for (int j = 0; j < 16; j++) { accT[j] = 0.f; accB[j] = 0.f; }

#pragma unroll 4
    for (int i = 0; i < 32; i++) {
        float4 zz = z4[i];

        // fp16 shadow copy (storage rounding only; dot math stays fp32)
        __half2 hlo = __floats2half2_rn(zz.x, zz.y);
        __half2 hhi = __floats2half2_rn(zz.z, zz.w);
        uint2 hpack;
        hpack.x = *reinterpret_cast<unsigned*>(&hlo);
        hpack.y = *reinterpret_cast<unsigned*>(&hhi);
        zh2[i] = hpack;

        float zv[4] = { zz.x, zz.y, zz.z, zz.w };
#pragma unroll
        for (int k = 0; k < 4; k++) {
            int d = i * 4 + k;
            const float4* wt4 = reinterpret_cast<const float4*>(&sW1[d * 16]);
            const float4* wb4 = reinterpret_cast<const float4*>(&sW1[(128 + d) * 16]);
#pragma unroll
            for (int q = 0; q < 4; q++) {
                float4 wt = wt4[q];
                float4 wb = wb4[q];
                accT[q * 4 + 0] = fmaf(zv[k], wt.x, accT[q * 4 + 0]);
                accT[q * 4 + 1] = fmaf(zv[k], wt.y, accT[q * 4 + 1]);
                accT[q * 4 + 2] = fmaf(zv[k], wt.z, accT[q * 4 + 2]);
                accT[q * 4 + 3] = fmaf(zv[k], wt.w, accT[q * 4 + 3]);
                accB[q * 4 + 0] = fmaf(zv[k], wb.x, accB[q * 4 + 0]);
                accB[q * 4 + 1] = fmaf(zv[k], wb.y, accB[q * 4 + 1]);
                accB[q * 4 + 2] = fmaf(zv[k], wb.z, accB[q * 4 + 2]);
                accB[q * 4 + 3] = fmaf(zv[k], wb.w, accB[q * 4 + 3]);
            }
        }
    }

    float4* P4 = reinterpret_cast<float4*>(g_P) + (size_t)n * 8;
#pragma unroll
    for (int q = 0; q < 4; q++) {
        P4[q]     = make_float4(accT[q*4+0], accT[q*4+1], accT[q*4+2], accT[q*4+3]);
        P4[4 + q] = make_float4(accB[q*4+0], accB[q*4+1], accB[q*4+2], accB[q*4+3]);
    }
}

// ---------------------------------------------------------------------------
// Kernel 2: per-edge work.  4 lanes per edge (lanes contiguous in a warp).
//   - adj_logits = dot(z_h[row], z_h[col])   (fp16 storage, fp32 math)
//   - h = relu(P_top[row] + P_bot[col] + b1) (16 units, 4 per lane, fp32)
//   - weights = softplus(h @ W2 + b2)
// out layout: [adj_logits (E), weights (E)]
// ---------------------------------------------------------------------------
__global__ __launch_bounds__(256)
void edge_kernel(const void* __restrict__ ei_raw,   // [2,E] int64 OR int32
                 const float* __restrict__ b1,
                 const float* __restrict__ W2,
                 const float* __restrict__ b2,
                 float* __restrict__ out,
                 int E, int N)
{
    int t   = blockIdx.x * blockDim.x + threadIdx.x;
    int e   = t >> 2;
    int sub = t & 3;
    bool valid = (e < E);
    int ec = valid ? e : (E - 1);   // clamp so all lanes stay active for shuffles

    int row, col;
    if (g_ei_is64) {
        const long long* ei = (const long long*)ei_raw;
        row = (int)ei[ec];
        col = (int)ei[(size_t)E + ec];
    } else {
        const int* ei = (const int*)ei_raw;
        row = ei[ec];
        col = ei[(size_t)E + ec];
    }
    row = min(max(row, 0), N - 1);
    col = min(max(col, 0), N - 1);

    // fp16 rows: 256 B each = 16 uint4; this lane reads 4 of them per side.
    const uint4* zr = reinterpret_cast<const uint4*>(g_zh) + (size_t)row * 16;
    const uint4* zc = reinterpret_cast<const uint4*>(g_zh) + (size_t)col * 16;

    float acc = 0.f;
#pragma unroll
    for (int i = 0; i < 4; i++) {
        uint4 au = zr[sub + 4 * i];
        uint4 bu = zc[sub + 4 * i];
        const unsigned aw[4] = { au.x, au.y, au.z, au.w };
        const unsigned bw[4] = { bu.x, bu.y, bu.z, bu.w };
#pragma unroll
        for (int k = 0; k < 4; k++) {
            float2 fa = __half22float2(*reinterpret_cast<const __half2*>(&aw[k]));
            float2 fb = __half22float2(*reinterpret_cast<const __half2*>(&bw[k]));
            acc = fmaf(fa.x, fb.x, acc);
            acc = fmaf(fa.y, fb.y, acc);
        }
    }
    acc += __shfl_xor_sync(0xffffffffu, acc, 1);
    acc += __shfl_xor_sync(0xffffffffu, acc, 2);

    // MLP: each lane covers 4 hidden units (fp32 path, unchanged)
    const float4* P4 = reinterpret_cast<const float4*>(g_P);
    float4 pr = P4[(size_t)row * 8 + sub];        // top part of P[row]
    float4 pc = P4[(size_t)col * 8 + 4 + sub];    // bottom part of P[col]
    float4 bb = reinterpret_cast<const float4*>(b1)[sub];
    float4 w2 = reinterpret_cast<const float4*>(W2)[sub];

    float h0 = fmaxf(pr.x + pc.x + bb.x, 0.f);
    float h1 = fmaxf(pr.y + pc.y + bb.y, 0.f);
    float h2 = fmaxf(pr.z + pc.z + bb.z, 0.f);
    float h3 = fmaxf(pr.w + pc.w + bb.w, 0.f);

    float part = h0 * w2.x + h1 * w2.y + h2 * w2.z + h3 * w2.w;
    part += __shfl_xor_sync(0xffffffffu, part, 1);
    part += __shfl_xor_sync(0xffffffffu, part, 2);

    if (valid && sub == 0) {
        float x = part + b2[0];
        // numerically stable softplus, matches jax.nn.softplus
        float w = fmaxf(x, 0.f) + log1pf(expf(-fabsf(x)));
        out[e]             = acc;
        out[(size_t)E + e] = w;
    }
}

// ---------------------------------------------------------------------------
// Launch
// ---------------------------------------------------------------------------
extern "C" void kernel_launch(void* const* d_in, const int* in_sizes, int n_in,
                              void* d_out, int out_size)
{
    const float* z  = (const float*)d_in[0];        // [N,128] f32
    const void*  ei = d_in[1];                      // [2,E]   i64 or i32
    const float* W1 = (const float*)d_in[2];        // [256,16] f32
    const float* b1 = (const float*)d_in[3];        // [16]
    const float* W2 = (const float*)d_in[4];        // [16,1]
    const float* b2 = (const float*)d_in[5];        // [1]
    float*       out = (float*)d_out;

    int N = in_sizes[0] / 128;
    int E = in_sizes[1] / 2;

    int blocks1 = (N + 255) / 256;
    proj_kernel<<<blocks1, 256>>>(z, W1, (const long long*)ei, N, E);

    long long threads2 = (long long)E * 4;
    int blocks2 = (int)((threads2 + 255) / 256);
    edge_kernel<<<blocks2, 256>>>(ei, b1, W2, b2, out, E, N);
}

// round 9
// speedup vs baseline: 1.1744x; 1.0781x over previous
#include <cuda_runtime.h>
#include <cuda_fp16.h>
#include <math.h>

// Scratch: per-node projections P[n][0:16] = z[n]@W1_top, P[n][16:32] = z[n]@W1_bot,
// plus an fp16 shadow copy of z for the adj_logits dot (halves gather traffic).
// Sized for N up to 131072 (actual N=100000).  256-byte aligned so per-edge
// 64B dot chunks and 128B P rows never straddle extra cache lines.
#define MAX_NODES (131072)
__device__ __align__(256) float  g_P [(size_t)MAX_NODES * 32];
__device__ __align__(256) __half g_zh[(size_t)MAX_NODES * 128];

// Flag: 1 if edge_index is stored as int64 on device, 0 if int32.
__device__ int g_ei_is64;

// ---------------------------------------------------------------------------
// Kernel 1: per-node projection + fp16 z shadow + edge-dtype detect.
// Block = 128 threads <-> 128 nodes.  z is staged through smem in 32-float
// K-chunks with fully coalesced global loads; the fp16 shadow is emitted
// coalesced during staging; P is written back through an smem transpose so
// its global stores coalesce as well.  W1 lives in smem (broadcast reads).
// Smem tile rows are padded to 36 words (144 B): keeps every row 16B-aligned
// for float4 LDS/STS (34 was 8B-aligned on odd rows -> misaligned trap) and
// 4t mod 32 banking keeps quarter-warp float4 phases conflict-free.
// ---------------------------------------------------------------------------
#define PBLK 128
#define TSTRIDE 36   // words per tile row (32 data + 4 pad; row = 144 B, 16B-aligned)

__global__ __launch_bounds__(PBLK)
void proj_kernel(const float* __restrict__ z,
                 const float* __restrict__ W1,   // [256,16] row-major
                 const long long* __restrict__ ei_as64,
                 int N, int E)
{
    __shared__ __align__(16) float sW1[256 * 16];        // 16 KB
    __shared__ __align__(16) float tile[PBLK * TSTRIDE]; // 18 KB

    // stage W1 (coalesced float4)
    {
        const float4* w4 = reinterpret_cast<const float4*>(W1);
        float4* s4 = reinterpret_cast<float4*>(sW1);
        for (int j = threadIdx.x; j < 1024; j += PBLK)
            s4[j] = w4[j];
    }

    // edge dtype detect (block 0, warp 0).  If the buffer were int32, an int64
    // read landing in [0,N) needs its high word == 0 (p ~ 2e-5); 32 hits in a
    // row is impossible.  Reads stay inside the first 256 bytes of either layout.
    if (blockIdx.x == 0 && threadIdx.x < 32) {
        int cnt = E < 32 ? E : 32;
        bool ok = true;
        if ((int)threadIdx.x < cnt) {
            long long v = ei_as64[threadIdx.x];
            ok = (v >= 0 && v < (long long)N);
        }
        unsigned m = __ballot_sync(0xffffffffu, ok);
        if (threadIdx.x == 0) g_ei_is64 = (m == 0xffffffffu) ? 1 : 0;
    }

    const int tid  = threadIdx.x;
    const int base = blockIdx.x * PBLK;

    float accT[16], accB[16];
#pragma unroll
    for (int j = 0; j < 16; j++) { accT[j] = 0.f; accB[j] = 0.f; }

    const float4* z4 = reinterpret_cast<const float4*>(z);

#pragma unroll
    for (int c = 0; c < 4; c++) {          // K-chunks of 32 floats
        __syncthreads();                    // tile reuse guard
        // ---- stage chunk: 128 rows x 8 float4, coalesced ----
#pragma unroll
        for (int j = 0; j < 8; j++) {
            int g  = tid + j * PBLK;        // 0..1023
            int r  = g >> 3;                // node row within block
            int c4 = g & 7;                 // float4 column within chunk
            int gr = base + r;
            int grc = gr < N ? gr : (N - 1);
            float4 v = z4[(size_t)grc * 32 + c * 8 + c4];
            *reinterpret_cast<float4*>(&tile[r * TSTRIDE + c4 * 4]) = v;
            if (gr < N) {
                // fp16 shadow, coalesced (8B per lane, 4 lines per warp-store)
                __half2 hlo = __floats2half2_rn(v.x, v.y);
                __half2 hhi = __floats2half2_rn(v.z, v.w);
                uint2 hp;
                hp.x = *reinterpret_cast<unsigned*>(&hlo);
                hp.y = *reinterpret_cast<unsigned*>(&hhi);
                *reinterpret_cast<uint2*>(
                    reinterpret_cast<char*>(g_zh) + (size_t)gr * 256 + c * 64 + c4 * 8) = hp;
            }
        }
        __syncthreads();
        // ---- compute this chunk's 32 K-elements for node tid ----
#pragma unroll
        for (int i = 0; i < 8; i++) {
            float4 zz = *reinterpret_cast<const float4*>(&tile[tid * TSTRIDE + i * 4]);
            float zv[4] = { zz.x, zz.y, zz.z, zz.w };
#pragma unroll
            for (int k = 0; k < 4; k++) {
                int d = c * 32 + i * 4 + k;
                const float4* wt4 = reinterpret_cast<const float4*>(&sW1[d * 16]);
                const float4* wb4 = reinterpret_cast<const float4*>(&sW1[(128 + d) * 16]);
#pragma unroll
                for (int q = 0; q < 4; q++) {
                    float4 wt = wt4[q];
                    float4 wb = wb4[q];
                    accT[q * 4 + 0] = fmaf(zv[k], wt.x, accT[q * 4 + 0]);
                    accT[q * 4 + 1] = fmaf(zv[k], wt.y, accT[q * 4 + 1]);
                    accT[q * 4 + 2] = fmaf(zv[k], wt.z, accT[q * 4 + 2]);
                    accT[q * 4 + 3] = fmaf(zv[k], wt.w, accT[q * 4 + 3]);
                    accB[q * 4 + 0] = fmaf(zv[k], wb.x, accB[q * 4 + 0]);
                    accB[q * 4 + 1] = fmaf(zv[k], wb.y, accB[q * 4 + 1]);
                    accB[q * 4 + 2] = fmaf(zv[k], wb.z, accB[q * 4 + 2]);
                    accB[q * 4 + 3] = fmaf(zv[k], wb.w, accB[q * 4 + 3]);
                }
            }
        }
    }

    // ---- write P through smem so the global stores coalesce ----
    __syncthreads();
#pragma unroll
    for (int q = 0; q < 4; q++) {
        *reinterpret_cast<float4*>(&tile[tid * TSTRIDE + q * 4]) =
            make_float4(accT[q*4+0], accT[q*4+1], accT[q*4+2], accT[q*4+3]);
        *reinterpret_cast<float4*>(&tile[tid * TSTRIDE + 16 + q * 4]) =
            make_float4(accB[q*4+0], accB[q*4+1], accB[q*4+2], accB[q*4+3]);
    }
    __syncthreads();
#pragma unroll
    for (int j = 0; j < 8; j++) {
        int g  = tid + j * PBLK;            // 0..1023
        int r  = g >> 3;
        int c4 = g & 7;
        int gr = base + r;
        if (gr < N)
            reinterpret_cast<float4*>(g_P)[(size_t)gr * 8 + c4] =
                *reinterpret_cast<const float4*>(&tile[r * TSTRIDE + c4 * 4]);
    }
}

// ---------------------------------------------------------------------------
// Kernel 2: per-edge work.  4 lanes per edge (lanes contiguous in a warp).
//   - adj_logits = dot(z_h[row], z_h[col])   (fp16 storage, fp32 math)
//   - h = relu(P_top[row] + P_bot[col] + b1) (16 units, 4 per lane, fp32)
//   - weights = softplus(h @ W2 + b2)
// out layout: [adj_logits (E), weights (E)]
// ---------------------------------------------------------------------------
__global__ __launch_bounds__(256)
void edge_kernel(const void* __restrict__ ei_raw,   // [2,E] int64 OR int32
                 const float* __restrict__ b1,
                 const float* __restrict__ W2,
                 const float* __restrict__ b2,
                 float* __restrict__ out,
                 int E, int N)
{
    int t   = blockIdx.x * blockDim.x + threadIdx.x;
    int e   = t >> 2;
    int sub = t & 3;
    bool valid = (e < E);
    int ec = valid ? e : (E - 1);   // clamp so all lanes stay active for shuffles

    int row, col;
    if (g_ei_is64) {
        const long long* ei = (const long long*)ei_raw;
        row = (int)ei[ec];
        col = (int)ei[(size_t)E + ec];
    } else {
        const int* ei = (const int*)ei_raw;
        row = ei[ec];
        col = ei[(size_t)E + ec];
    }
    row = min(max(row, 0), N - 1);
    col = min(max(col, 0), N - 1);

    // fp16 rows: 256 B each = 16 uint4; this lane reads 4 of them per side.
    const uint4* zr = reinterpret_cast<const uint4*>(g_zh) + (size_t)row * 16;
    const uint4* zc = reinterpret_cast<const uint4*>(g_zh) + (size_t)col * 16;

    float acc = 0.f;
#pragma unroll
    for (int i = 0; i < 4; i++) {
        uint4 au = zr[sub + 4 * i];
        uint4 bu = zc[sub + 4 * i];
        const unsigned aw[4] = { au.x, au.y, au.z, au.w };
        const unsigned bw[4] = { bu.x, bu.y, bu.z, bu.w };
#pragma unroll
        for (int k = 0; k < 4; k++) {
            float2 fa = __half22float2(*reinterpret_cast<const __half2*>(&aw[k]));
            float2 fb = __half22float2(*reinterpret_cast<const __half2*>(&bw[k]));
            acc = fmaf(fa.x, fb.x, acc);
            acc = fmaf(fa.y, fb.y, acc);
        }
    }
    acc += __shfl_xor_sync(0xffffffffu, acc, 1);
    acc += __shfl_xor_sync(0xffffffffu, acc, 2);

    // MLP: each lane covers 4 hidden units (fp32 path)
    const float4* P4 = reinterpret_cast<const float4*>(g_P);
    float4 pr = P4[(size_t)row * 8 + sub];        // top part of P[row]
    float4 pc = P4[(size_t)col * 8 + 4 + sub];    // bottom part of P[col]
    float4 bb = reinterpret_cast<const float4*>(b1)[sub];
    float4 w2 = reinterpret_cast<const float4*>(W2)[sub];

    float h0 = fmaxf(pr.x + pc.x + bb.x, 0.f);
    float h1 = fmaxf(pr.y + pc.y + bb.y, 0.f);
    float h2 = fmaxf(pr.z + pc.z + bb.z, 0.f);
    float h3 = fmaxf(pr.w + pc.w + bb.w, 0.f);

    float part = h0 * w2.x + h1 * w2.y + h2 * w2.z + h3 * w2.w;
    part += __shfl_xor_sync(0xffffffffu, part, 1);
    part += __shfl_xor_sync(0xffffffffu, part, 2);

    if (valid && sub == 0) {
        float x = part + b2[0];
        // numerically stable softplus, matches jax.nn.softplus
        float w = fmaxf(x, 0.f) + log1pf(expf(-fabsf(x)));
        out[e]             = acc;
        out[(size_t)E + e] = w;
    }
}

// ---------------------------------------------------------------------------
// Launch
// ---------------------------------------------------------------------------
extern "C" void kernel_launch(void* const* d_in, const int* in_sizes, int n_in,
                              void* d_out, int out_size)
{
    const float* z  = (const float*)d_in[0];        // [N,128] f32
    const void*  ei = d_in[1];                      // [2,E]   i64 or i32
    const float* W1 = (const float*)d_in[2];        // [256,16] f32
    const float* b1 = (const float*)d_in[3];        // [16]
    const float* W2 = (const float*)d_in[4];        // [16,1]
    const float* b2 = (const float*)d_in[5];        // [1]
    float*       out = (float*)d_out;

    int N = in_sizes[0] / 128;
    int E = in_sizes[1] / 2;

    int blocks1 = (N + PBLK - 1) / PBLK;
    proj_kernel<<<blocks1, PBLK>>>(z, W1, (const long long*)ei, N, E);

    long long threads2 = (long long)E * 4;
    int blocks2 = (int)((threads2 + 255) / 256);
    edge_kernel<<<blocks2, 256>>>(ei, b1, W2, b2, out, E, N);
}

// round 10
// speedup vs baseline: 1.2101x; 1.0304x over previous
#include <cuda_runtime.h>
#include <cuda_fp16.h>
#include <math.h>

// Scratch: per-node projections P[n][0:16] = z[n]@W1_top, P[n][16:32] = z[n]@W1_bot,
// plus an fp16 shadow copy of z for the adj_logits dot (halves gather traffic).
// Sized for N up to 131072 (actual N=100000).
#define MAX_NODES (131072)
__device__ __align__(256) float  g_P [(size_t)MAX_NODES * 32];
__device__ __align__(256) __half g_zh[(size_t)MAX_NODES * 128];

// Flag: 1 if edge_index is stored as int64 on device, 0 if int32.
__device__ int g_ei_is64;

// ---------------------------------------------------------------------------
// Kernel 1: per-node projection + fp16 z shadow + edge-dtype detect.
// Block = 128 threads <-> 128 nodes.  z staged through smem in 32-float
// K-chunks; global loads for chunk c+1 are PREFETCHED into registers while
// chunk c computes, hiding DRAM latency under the FFMA stream.
// Tile rows padded to 36 words (144 B, 16B-aligned; conflict-free float4).
// ---------------------------------------------------------------------------
#define PBLK 128
#define TSTRIDE 36

__global__ __launch_bounds__(PBLK)
void proj_kernel(const float* __restrict__ z,
                 const float* __restrict__ W1,   // [256,16] row-major
                 const long long* __restrict__ ei_as64,
                 int N, int E)
{
    __shared__ __align__(16) float sW1[256 * 16];        // 16 KB
    __shared__ __align__(16) float tile[PBLK * TSTRIDE]; // 18 KB

    // stage W1 (coalesced float4)
    {
        const float4* w4 = reinterpret_cast<const float4*>(W1);
        float4* s4 = reinterpret_cast<float4*>(sW1);
        for (int j = threadIdx.x; j < 1024; j += PBLK)
            s4[j] = w4[j];
    }

    // edge dtype detect (block 0, warp 0); see prior-round rationale.
    if (blockIdx.x == 0 && threadIdx.x < 32) {
        int cnt = E < 32 ? E : 32;
        bool ok = true;
        if ((int)threadIdx.x < cnt) {
            long long v = ei_as64[threadIdx.x];
            ok = (v >= 0 && v < (long long)N);
        }
        unsigned m = __ballot_sync(0xffffffffu, ok);
        if (threadIdx.x == 0) g_ei_is64 = (m == 0xffffffffu) ? 1 : 0;
    }

    const int tid  = threadIdx.x;
    const int base = blockIdx.x * PBLK;
    const float4* z4 = reinterpret_cast<const float4*>(z);

    // per-thread coalesced slice mapping: element j -> row r=g>>3, col c4=g&7
    int rr[8], cc[8], grN[8];
    size_t gidx[8];
#pragma unroll
    for (int j = 0; j < 8; j++) {
        int g  = tid + j * PBLK;
        rr[j]  = g >> 3;
        cc[j]  = g & 7;
        int gr = base + rr[j];
        grN[j] = gr;
        int grc = gr < N ? gr : (N - 1);
        gidx[j] = (size_t)grc * 32 + cc[j];
    }

    float accT[16], accB[16];
#pragma unroll
    for (int j = 0; j < 16; j++) { accT[j] = 0.f; accB[j] = 0.f; }

    // prefetch chunk 0
    float4 pre[8];
#pragma unroll
    for (int j = 0; j < 8; j++) pre[j] = z4[gidx[j] + 0 * 8];

#pragma unroll
    for (int c = 0; c < 4; c++) {
        __syncthreads();   // previous compute done reading tile (and W1 staged)
        // store prefetched chunk to tile + emit fp16 shadow (coalesced)
#pragma unroll
        for (int j = 0; j < 8; j++) {
            float4 v = pre[j];
            *reinterpret_cast<float4*>(&tile[rr[j] * TSTRIDE + cc[j] * 4]) = v;
            if (grN[j] < N) {
                __half2 hlo = __floats2half2_rn(v.x, v.y);
                __half2 hhi = __floats2half2_rn(v.z, v.w);
                uint2 hp;
                hp.x = *reinterpret_cast<unsigned*>(&hlo);
                hp.y = *reinterpret_cast<unsigned*>(&hhi);
                *reinterpret_cast<uint2*>(
                    reinterpret_cast<char*>(g_zh) + (size_t)grN[j] * 256 + c * 64 + cc[j] * 8) = hp;
            }
        }
        // issue next chunk's global loads (in flight during compute below)
        if (c < 3) {
#pragma unroll
            for (int j = 0; j < 8; j++) pre[j] = z4[gidx[j] + (c + 1) * 8];
        }
        __syncthreads();
        // compute this chunk's 32 K-elements for node `tid`
#pragma unroll
        for (int i = 0; i < 8; i++) {
            float4 zz = *reinterpret_cast<const float4*>(&tile[tid * TSTRIDE + i * 4]);
            float zv[4] = { zz.x, zz.y, zz.z, zz.w };
#pragma unroll
            for (int k = 0; k < 4; k++) {
                int d = c * 32 + i * 4 + k;
                const float4* wt4 = reinterpret_cast<const float4*>(&sW1[d * 16]);
                const float4* wb4 = reinterpret_cast<const float4*>(&sW1[(128 + d) * 16]);
#pragma unroll
                for (int q = 0; q < 4; q++) {
                    float4 wt = wt4[q];
                    float4 wb = wb4[q];
                    accT[q * 4 + 0] = fmaf(zv[k], wt.x, accT[q * 4 + 0]);
                    accT[q * 4 + 1] = fmaf(zv[k], wt.y, accT[q * 4 + 1]);
                    accT[q * 4 + 2] = fmaf(zv[k], wt.z, accT[q * 4 + 2]);
                    accT[q * 4 + 3] = fmaf(zv[k], wt.w, accT[q * 4 + 3]);
                    accB[q * 4 + 0] = fmaf(zv[k], wb.x, accB[q * 4 + 0]);
                    accB[q * 4 + 1] = fmaf(zv[k], wb.y, accB[q * 4 + 1]);
                    accB[q * 4 + 2] = fmaf(zv[k], wb.z, accB[q * 4 + 2]);
                    accB[q * 4 + 3] = fmaf(zv[k], wb.w, accB[q * 4 + 3]);
                }
            }
        }
    }

    // write P through smem so the global stores coalesce
    __syncthreads();
#pragma unroll
    for (int q = 0; q < 4; q++) {
        *reinterpret_cast<float4*>(&tile[tid * TSTRIDE + q * 4]) =
            make_float4(accT[q*4+0], accT[q*4+1], accT[q*4+2], accT[q*4+3]);
        *reinterpret_cast<float4*>(&tile[tid * TSTRIDE + 16 + q * 4]) =
            make_float4(accB[q*4+0], accB[q*4+1], accB[q*4+2], accB[q*4+3]);
    }
    __syncthreads();
#pragma unroll
    for (int j = 0; j < 8; j++) {
        if (grN[j] < N)
            reinterpret_cast<float4*>(g_P)[(size_t)grN[j] * 8 + cc[j]] =
                *reinterpret_cast<const float4*>(&tile[rr[j] * TSTRIDE + cc[j] * 4]);
    }
}

// ---------------------------------------------------------------------------
// Kernel 2: per-edge work.  8 lanes per edge so every dot-load warp
// instruction covers a FULL 128B line per edge (4 edges/warp, 4 lines/instr):
//   - adj_logits = dot(z_h[row], z_h[col])   (fp16 storage, fp32 math)
//   - h = relu(P_top[row] + P_bot[col] + b1) (16 units, 2 per lane, fp32)
//   - weights = softplus(h @ W2 + b2)
// out layout: [adj_logits (E), weights (E)]
// ---------------------------------------------------------------------------
__global__ __launch_bounds__(256)
void edge_kernel(const void* __restrict__ ei_raw,   // [2,E] int64 OR int32
                 const float* __restrict__ b1,
                 const float* __restrict__ W2,
                 const float* __restrict__ b2,
                 float* __restrict__ out,
                 int E, int N)
{
    int t   = blockIdx.x * blockDim.x + threadIdx.x;
    int e   = t >> 3;
    int sub = t & 7;
    bool valid = (e < E);
    int ec = valid ? e : (E - 1);   // clamp so all lanes stay active for shuffles

    int row, col;
    if (g_ei_is64) {
        const long long* ei = (const long long*)ei_raw;
        row = (int)ei[ec];
        col = (int)ei[(size_t)E + ec];
    } else {
        const int* ei = (const int*)ei_raw;
        row = ei[ec];
        col = ei[(size_t)E + ec];
    }
    row = min(max(row, 0), N - 1);
    col = min(max(col, 0), N - 1);

    // fp16 rows: 256 B each = 16 uint4; lane reads uint4 sub and sub+8.
    const uint4* zr = reinterpret_cast<const uint4*>(g_zh) + (size_t)row * 16;
    const uint4* zc = reinterpret_cast<const uint4*>(g_zh) + (size_t)col * 16;

    float acc = 0.f;
#pragma unroll
    for (int i = 0; i < 2; i++) {
        uint4 au = zr[sub + 8 * i];
        uint4 bu = zc[sub + 8 * i];
        const unsigned aw[4] = { au.x, au.y, au.z, au.w };
        const unsigned bw[4] = { bu.x, bu.y, bu.z, bu.w };
#pragma unroll
        for (int k = 0; k < 4; k++) {
            float2 fa = __half22float2(*reinterpret_cast<const __half2*>(&aw[k]));
            float2 fb = __half22float2(*reinterpret_cast<const __half2*>(&bw[k]));
            acc = fmaf(fa.x, fb.x, acc);
            acc = fmaf(fa.y, fb.y, acc);
        }
    }
    acc += __shfl_xor_sync(0xffffffffu, acc, 1);
    acc += __shfl_xor_sync(0xffffffffu, acc, 2);
    acc += __shfl_xor_sync(0xffffffffu, acc, 4);

    // MLP: each lane covers 2 hidden units (float2 loads)
    const float2* P2 = reinterpret_cast<const float2*>(g_P);
    float2 pr = P2[(size_t)row * 16 + sub];        // top half of P[row]
    float2 pc = P2[(size_t)col * 16 + 8 + sub];    // bottom half of P[col]
    float2 bb = reinterpret_cast<const float2*>(b1)[sub];
    float2 w2 = reinterpret_cast<const float2*>(W2)[sub];

    float h0 = fmaxf(pr.x + pc.x + bb.x, 0.f);
    float h1 = fmaxf(pr.y + pc.y + bb.y, 0.f);

    float part = h0 * w2.x + h1 * w2.y;
    part += __shfl_xor_sync(0xffffffffu, part, 1);
    part += __shfl_xor_sync(0xffffffffu, part, 2);
    part += __shfl_xor_sync(0xffffffffu, part, 4);

    if (valid && sub == 0) {
        float x = part + b2[0];
        // numerically stable softplus, matches jax.nn.softplus
        float w = fmaxf(x, 0.f) + log1pf(expf(-fabsf(x)));
        out[e]             = acc;
        out[(size_t)E + e] = w;
    }
}

// ---------------------------------------------------------------------------
// Launch
// ---------------------------------------------------------------------------
extern "C" void kernel_launch(void* const* d_in, const int* in_sizes, int n_in,
                              void* d_out, int out_size)
{
    const float* z  = (const float*)d_in[0];        // [N,128] f32
    const void*  ei = d_in[1];                      // [2,E]   i64 or i32
    const float* W1 = (const float*)d_in[2];        // [256,16] f32
    const float* b1 = (const float*)d_in[3];        // [16]
    const float* W2 = (const float*)d_in[4];        // [16,1]
    const float* b2 = (const float*)d_in[5];        // [1]
    float*       out = (float*)d_out;

    int N = in_sizes[0] / 128;
    int E = in_sizes[1] / 2;

    int blocks1 = (N + PBLK - 1) / PBLK;
    proj_kernel<<<blocks1, PBLK>>>(z, W1, (const long long*)ei, N, E);

    long long threads2 = (long long)E * 8;
    int blocks2 = (int)((threads2 + 255) / 256);
    edge_kernel<<<blocks2, 256>>>(ei, b1, W2, b2, out, E, N);
}

// round 11
// speedup vs baseline: 1.2814x; 1.0589x over previous
#include <cuda_runtime.h>
#include <cuda_fp16.h>
#include <math.h>

// Scratch: per-node projections P[n][0:16] = z[n]@W1_top, P[n][16:32] = z[n]@W1_bot,
// plus an fp16 shadow copy of z for the adj_logits dot (halves gather traffic).
// Sized for N up to 131072 (actual N=100000).
#define MAX_NODES (131072)
__device__ __align__(256) float  g_P [(size_t)MAX_NODES * 32];
__device__ __align__(256) __half g_zh[(size_t)MAX_NODES * 128];

// Flag: 1 if edge_index is stored as int64 on device, 0 if int32.
__device__ int g_ei_is64;

// ---------------------------------------------------------------------------
// Packed fp32x2 helpers (FFMA2 — only reachable via PTX fma.rn.f32x2).
// Bit-exact vs two scalar fp32 FMAs; halves the fma-pipe instruction count.
// ---------------------------------------------------------------------------
__device__ __forceinline__ void ffma2(unsigned long long& d,
                                      unsigned long long a,
                                      unsigned long long b)
{
    asm("fma.rn.f32x2 %0, %1, %2, %0;" : "+l"(d) : "l"(a), "l"(b));
}
__device__ __forceinline__ unsigned long long pk2(float v)
{
    unsigned long long r;
    asm("mov.b64 %0, {%1, %1};" : "=l"(r) : "f"(v));
    return r;
}

// ---------------------------------------------------------------------------
// Kernel 1: per-node projection + fp16 z shadow + edge-dtype detect.
// Block = 128 threads <-> 128 nodes.  z staged through smem in 32-float
// K-chunks with register prefetch of the next chunk; inner product uses
// packed fp32x2 FMAs.  Tile rows padded to 36 words (144 B, 16B-aligned).
// ---------------------------------------------------------------------------
#define PBLK 128
#define TSTRIDE 36

__global__ __launch_bounds__(PBLK)
void proj_kernel(const float* __restrict__ z,
                 const float* __restrict__ W1,   // [256,16] row-major
                 const long long* __restrict__ ei_as64,
                 int N, int E)
{
    __shared__ __align__(16) float sW1[256 * 16];        // 16 KB
    __shared__ __align__(16) float tile[PBLK * TSTRIDE]; // 18 KB

    // stage W1 (coalesced float4)
    {
        const float4* w4 = reinterpret_cast<const float4*>(W1);
        float4* s4 = reinterpret_cast<float4*>(sW1);
        for (int j = threadIdx.x; j < 1024; j += PBLK)
            s4[j] = w4[j];
    }

    // edge dtype detect (block 0, warp 0); see prior-round rationale.
    if (blockIdx.x == 0 && threadIdx.x < 32) {
        int cnt = E < 32 ? E : 32;
        bool ok = true;
        if ((int)threadIdx.x < cnt) {
            long long v = ei_as64[threadIdx.x];
            ok = (v >= 0 && v < (long long)N);
        }
        unsigned m = __ballot_sync(0xffffffffu, ok);
        if (threadIdx.x == 0) g_ei_is64 = (m == 0xffffffffu) ? 1 : 0;
    }

    const int tid  = threadIdx.x;
    const int base = blockIdx.x * PBLK;
    const float4* z4 = reinterpret_cast<const float4*>(z);

    // per-thread coalesced slice mapping: element j -> row r=g>>3, col c4=g&7
    int rr[8], cc[8], grN[8];
    size_t gidx[8];
#pragma unroll
    for (int j = 0; j < 8; j++) {
        int g  = tid + j * PBLK;
        rr[j]  = g >> 3;
        cc[j]  = g & 7;
        int gr = base + rr[j];
        grN[j] = gr;
        int grc = gr < N ? gr : (N - 1);
        gidx[j] = (size_t)grc * 32 + cc[j];
    }

    // 16 packed accumulators = 32 fp32 lanes: accT2[j] holds T(2j),T(2j+1)
    unsigned long long accT2[8], accB2[8];
#pragma unroll
    for (int j = 0; j < 8; j++) { accT2[j] = 0ull; accB2[j] = 0ull; }

    // prefetch chunk 0
    float4 pre[8];
#pragma unroll
    for (int j = 0; j < 8; j++) pre[j] = z4[gidx[j] + 0 * 8];

#pragma unroll
    for (int c = 0; c < 4; c++) {
        __syncthreads();   // previous compute done reading tile (and W1 staged)
        // store prefetched chunk to tile + emit fp16 shadow (coalesced)
#pragma unroll
        for (int j = 0; j < 8; j++) {
            float4 v = pre[j];
            *reinterpret_cast<float4*>(&tile[rr[j] * TSTRIDE + cc[j] * 4]) = v;
            if (grN[j] < N) {
                __half2 hlo = __floats2half2_rn(v.x, v.y);
                __half2 hhi = __floats2half2_rn(v.z, v.w);
                uint2 hp;
                hp.x = *reinterpret_cast<unsigned*>(&hlo);
                hp.y = *reinterpret_cast<unsigned*>(&hhi);
                *reinterpret_cast<uint2*>(
                    reinterpret_cast<char*>(g_zh) + (size_t)grN[j] * 256 + c * 64 + cc[j] * 8) = hp;
            }
        }
        // issue next chunk's global loads (in flight during compute below)
        if (c < 3) {
#pragma unroll
            for (int j = 0; j < 8; j++) pre[j] = z4[gidx[j] + (c + 1) * 8];
        }
        __syncthreads();
        // compute this chunk's 32 K-elements for node `tid` (packed fp32x2)
#pragma unroll
        for (int i = 0; i < 8; i++) {
            float4 zz = *reinterpret_cast<const float4*>(&tile[tid * TSTRIDE + i * 4]);
            float zv[4] = { zz.x, zz.y, zz.z, zz.w };
#pragma unroll
            for (int k = 0; k < 4; k++) {
                int d = c * 32 + i * 4 + k;
                unsigned long long zp = pk2(zv[k]);
                const ulonglong2* wt = reinterpret_cast<const ulonglong2*>(&sW1[d * 16]);
                const ulonglong2* wb = reinterpret_cast<const ulonglong2*>(&sW1[(128 + d) * 16]);
#pragma unroll
                for (int q = 0; q < 4; q++) {
                    ulonglong2 pt = wt[q];
                    ulonglong2 pb = wb[q];
                    ffma2(accT2[q * 2 + 0], zp, pt.x);
                    ffma2(accT2[q * 2 + 1], zp, pt.y);
                    ffma2(accB2[q * 2 + 0], zp, pb.x);
                    ffma2(accB2[q * 2 + 1], zp, pb.y);
                }
            }
        }
    }

    // write P through smem so the global stores coalesce
    // (packed pairs are adjacent floats, so layout is unchanged)
    __syncthreads();
#pragma unroll
    for (int q = 0; q < 4; q++) {
        ulonglong2 t; t.x = accT2[q * 2]; t.y = accT2[q * 2 + 1];
        ulonglong2 b; b.x = accB2[q * 2]; b.y = accB2[q * 2 + 1];
        *reinterpret_cast<ulonglong2*>(&tile[tid * TSTRIDE + q * 4])      = t;
        *reinterpret_cast<ulonglong2*>(&tile[tid * TSTRIDE + 16 + q * 4]) = b;
    }
    __syncthreads();
#pragma unroll
    for (int j = 0; j < 8; j++) {
        if (grN[j] < N)
            reinterpret_cast<float4*>(g_P)[(size_t)grN[j] * 8 + cc[j]] =
                *reinterpret_cast<const float4*>(&tile[rr[j] * TSTRIDE + cc[j] * 4]);
    }
}

// ---------------------------------------------------------------------------
// Kernel 2: per-edge work.  8 lanes per edge (unchanged from round 10):
//   - adj_logits = dot(z_h[row], z_h[col])   (fp16 storage, fp32 math)
//   - h = relu(P_top[row] + P_bot[col] + b1) (16 units, 2 per lane, fp32)
//   - weights = softplus(h @ W2 + b2)
// out layout: [adj_logits (E), weights (E)]
// ---------------------------------------------------------------------------
__global__ __launch_bounds__(256)
void edge_kernel(const void* __restrict__ ei_raw,   // [2,E] int64 OR int32
                 const float* __restrict__ b1,
                 const float* __restrict__ W2,
                 const float* __restrict__ b2,
                 float* __restrict__ out,
                 int E, int N)
{
    int t   = blockIdx.x * blockDim.x + threadIdx.x;
    int e   = t >> 3;
    int sub = t & 7;
    bool valid = (e < E);
    int ec = valid ? e : (E - 1);   // clamp so all lanes stay active for shuffles

    int row, col;
    if (g_ei_is64) {
        const long long* ei = (const long long*)ei_raw;
        row = (int)ei[ec];
        col = (int)ei[(size_t)E + ec];
    } else {
        const int* ei = (const int*)ei_raw;
        row = ei[ec];
        col = ei[(size_t)E + ec];
    }
    row = min(max(row, 0), N - 1);
    col = min(max(col, 0), N - 1);

    // fp16 rows: 256 B each = 16 uint4; lane reads uint4 sub and sub+8.
    const uint4* zr = reinterpret_cast<const uint4*>(g_zh) + (size_t)row * 16;
    const uint4* zc = reinterpret_cast<const uint4*>(g_zh) + (size_t)col * 16;

    float acc = 0.f;
#pragma unroll
    for (int i = 0; i < 2; i++) {
        uint4 au = zr[sub + 8 * i];
        uint4 bu = zc[sub + 8 * i];
        const unsigned aw[4] = { au.x, au.y, au.z, au.w };
        const unsigned bw[4] = { bu.x, bu.y, bu.z, bu.w };
#pragma unroll
        for (int k = 0; k < 4; k++) {
            float2 fa = __half22float2(*reinterpret_cast<const __half2*>(&aw[k]));
            float2 fb = __half22float2(*reinterpret_cast<const __half2*>(&bw[k]));
            acc = fmaf(fa.x, fb.x, acc);
            acc = fmaf(fa.y, fb.y, acc);
        }
    }
    acc += __shfl_xor_sync(0xffffffffu, acc, 1);
    acc += __shfl_xor_sync(0xffffffffu, acc, 2);
    acc += __shfl_xor_sync(0xffffffffu, acc, 4);

    // MLP: each lane covers 2 hidden units (float2 loads)
    const float2* P2 = reinterpret_cast<const float2*>(g_P);
    float2 pr = P2[(size_t)row * 16 + sub];        // top half of P[row]
    float2 pc = P2[(size_t)col * 16 + 8 + sub];    // bottom half of P[col]
    float2 bb = reinterpret_cast<const float2*>(b1)[sub];
    float2 w2 = reinterpret_cast<const float2*>(W2)[sub];

    float h0 = fmaxf(pr.x + pc.x + bb.x, 0.f);
    float h1 = fmaxf(pr.y + pc.y + bb.y, 0.f);

    float part = h0 * w2.x + h1 * w2.y;
    part += __shfl_xor_sync(0xffffffffu, part, 1);
    part += __shfl_xor_sync(0xffffffffu, part, 2);
    part += __shfl_xor_sync(0xffffffffu, part, 4);

    if (valid && sub == 0) {
        float x = part + b2[0];
        // numerically stable softplus, matches jax.nn.softplus
        float w = fmaxf(x, 0.f) + log1pf(expf(-fabsf(x)));
        out[e]             = acc;
        out[(size_t)E + e] = w;
    }
}

// ---------------------------------------------------------------------------
// Launch
// ---------------------------------------------------------------------------
extern "C" void kernel_launch(void* const* d_in, const int* in_sizes, int n_in,
                              void* d_out, int out_size)
{
    const float* z  = (const float*)d_in[0];        // [N,128] f32
    const void*  ei = d_in[1];                      // [2,E]   i64 or i32
    const float* W1 = (const float*)d_in[2];        // [256,16] f32
    const float* b1 = (const float*)d_in[3];        // [16]
    const float* W2 = (const float*)d_in[4];        // [16,1]
    const float* b2 = (const float*)d_in[5];        // [1]
    float*       out = (float*)d_out;

    int N = in_sizes[0] / 128;
    int E = in_sizes[1] / 2;

    int blocks1 = (N + PBLK - 1) / PBLK;
    proj_kernel<<<blocks1, PBLK>>>(z, W1, (const long long*)ei, N, E);

    long long threads2 = (long long)E * 8;
    int blocks2 = (int)((threads2 + 255) / 256);
    edge_kernel<<<blocks2, 256>>>(ei, b1, W2, b2, out, E, N);
}

// round 12
// speedup vs baseline: 1.3275x; 1.0360x over previous
#include <cuda_runtime.h>
#include <cuda_fp16.h>
#include <math.h>

// Scratch: per-node projections P[n][0:16] = z[n]@W1_top, P[n][16:32] = z[n]@W1_bot,
// plus an fp16 shadow copy of z for the adj_logits dot.
#define MAX_NODES (131072)
__device__ __align__(256) float  g_P [(size_t)MAX_NODES * 32];
__device__ __align__(256) __half g_zh[(size_t)MAX_NODES * 128];

__device__ int g_ei_is64;

// Packed fp32x2 FMA (bit-exact vs two scalar FMAs; saves issue slots)
__device__ __forceinline__ void ffma2(unsigned long long& d,
                                      unsigned long long a,
                                      unsigned long long b)
{
    asm("fma.rn.f32x2 %0, %1, %2, %0;" : "+l"(d) : "l"(a), "l"(b));
}
__device__ __forceinline__ unsigned long long pk2(float v)
{
    unsigned long long r;
    asm("mov.b64 %0, {%1, %1};" : "=l"(r) : "f"(v));
    return r;
}

// ---------------------------------------------------------------------------
// Kernel 1: projection, 2 nodes per thread (halves W1 smem-load count/node).
// Block = 128 threads <-> 256 nodes.  z staged through smem in 16-float
// K-chunks (coalesced); fp16 shadow emitted during staging; P written back
// through smem in two passes so stores coalesce.  Static smem = 36 KB.
// ---------------------------------------------------------------------------
#define PBLK 128
#define NPB  256
#define TS2  20    // tile words/row (16 data + 4 pad; 80 B rows, 16B-aligned)

__global__ __launch_bounds__(PBLK)
void proj_kernel(const float* __restrict__ z,
                 const float* __restrict__ W1,   // [256,16] row-major
                 const long long* __restrict__ ei_as64,
                 int N, int E)
{
    __shared__ __align__(16) float sW1[256 * 16];     // 16 KB
    __shared__ __align__(16) float tile[NPB * TS2];   // 20 KB

    // stage W1 (coalesced float4)
    {
        const float4* w4 = reinterpret_cast<const float4*>(W1);
        float4* s4 = reinterpret_cast<float4*>(sW1);
        for (int j = threadIdx.x; j < 1024; j += PBLK)
            s4[j] = w4[j];
    }

    // edge dtype detect (block 0, warp 0); see prior-round rationale.
    if (blockIdx.x == 0 && threadIdx.x < 32) {
        int cnt = E < 32 ? E : 32;
        bool ok = true;
        if ((int)threadIdx.x < cnt) {
            long long v = ei_as64[threadIdx.x];
            ok = (v >= 0 && v < (long long)N);
        }
        unsigned m = __ballot_sync(0xffffffffu, ok);
        if (threadIdx.x == 0) g_ei_is64 = (m == 0xffffffffu) ? 1 : 0;
    }

    const int tid  = threadIdx.x;
    const int base = blockIdx.x * NPB;
    const float4* z4 = reinterpret_cast<const float4*>(z);

    // staging slice mapping: element j -> row r=g>>2 (0..255), col c4=g&3
    int rr[8], cc[8], grN[8];
#pragma unroll
    for (int j = 0; j < 8; j++) {
        int g  = tid + j * PBLK;
        rr[j]  = g >> 2;
        cc[j]  = g & 3;
        grN[j] = base + rr[j];
    }

    // two nodes per thread: a = base+tid, b = base+tid+128
    unsigned long long aT2[8], aB2[8], bT2[8], bB2[8];
#pragma unroll
    for (int j = 0; j < 8; j++) { aT2[j]=0ull; aB2[j]=0ull; bT2[j]=0ull; bB2[j]=0ull; }

#pragma unroll
    for (int c = 0; c < 8; c++) {           // 8 chunks x 16 K-floats
        __syncthreads();
#pragma unroll
        for (int j = 0; j < 8; j++) {
            int gr  = grN[j];
            int grc = gr < N ? gr : (N - 1);
            float4 v = z4[(size_t)grc * 32 + c * 4 + cc[j]];
            *reinterpret_cast<float4*>(&tile[rr[j] * TS2 + cc[j] * 4]) = v;
            if (gr < N) {
                __half2 hlo = __floats2half2_rn(v.x, v.y);
                __half2 hhi = __floats2half2_rn(v.z, v.w);
                uint2 hp;
                hp.x = *reinterpret_cast<unsigned*>(&hlo);
                hp.y = *reinterpret_cast<unsigned*>(&hhi);
                *reinterpret_cast<uint2*>(
                    reinterpret_cast<char*>(g_zh) + (size_t)gr * 256 + c * 32 + cc[j] * 8) = hp;
            }
        }
        __syncthreads();
#pragma unroll
        for (int i = 0; i < 4; i++) {
            float4 za = *reinterpret_cast<const float4*>(&tile[tid * TS2 + i * 4]);
            float4 zb = *reinterpret_cast<const float4*>(&tile[(tid + PBLK) * TS2 + i * 4]);
            float av[4] = { za.x, za.y, za.z, za.w };
            float bv[4] = { zb.x, zb.y, zb.z, zb.w };
#pragma unroll
            for (int k = 0; k < 4; k++) {
                int d = c * 16 + i * 4 + k;
                unsigned long long zpa = pk2(av[k]);
                unsigned long long zpb = pk2(bv[k]);
                const ulonglong2* wt = reinterpret_cast<const ulonglong2*>(&sW1[d * 16]);
                const ulonglong2* wb = reinterpret_cast<const ulonglong2*>(&sW1[(128 + d) * 16]);
#pragma unroll
                for (int q = 0; q < 4; q++) {
                    ulonglong2 pt = wt[q];
                    ulonglong2 pb = wb[q];
                    ffma2(aT2[q*2+0], zpa, pt.x); ffma2(aT2[q*2+1], zpa, pt.y);
                    ffma2(bT2[q*2+0], zpb, pt.x); ffma2(bT2[q*2+1], zpb, pt.y);
                    ffma2(aB2[q*2+0], zpa, pb.x); ffma2(aB2[q*2+1], zpa, pb.y);
                    ffma2(bB2[q*2+0], zpb, pb.x); ffma2(bB2[q*2+1], zpb, pb.y);
                }
            }
        }
    }

    // P writeback via smem, two passes (top 16, bottom 16), coalesced stores
    float4* gP4 = reinterpret_cast<float4*>(g_P);

    __syncthreads();
#pragma unroll
    for (int q = 0; q < 4; q++) {
        ulonglong2 ta; ta.x = aT2[q*2]; ta.y = aT2[q*2+1];
        ulonglong2 tb; tb.x = bT2[q*2]; tb.y = bT2[q*2+1];
        *reinterpret_cast<ulonglong2*>(&tile[tid * TS2 + q * 4])          = ta;
        *reinterpret_cast<ulonglong2*>(&tile[(tid + PBLK) * TS2 + q * 4]) = tb;
    }
    __syncthreads();
#pragma unroll
    for (int j = 0; j < 8; j++)
        if (grN[j] < N)
            gP4[(size_t)grN[j] * 8 + cc[j]] =
                *reinterpret_cast<const float4*>(&tile[rr[j] * TS2 + cc[j] * 4]);

    __syncthreads();
#pragma unroll
    for (int q = 0; q < 4; q++) {
        ulonglong2 ba; ba.x = aB2[q*2]; ba.y = aB2[q*2+1];
        ulonglong2 bb; bb.x = bB2[q*2]; bb.y = bB2[q*2+1];
        *reinterpret_cast<ulonglong2*>(&tile[tid * TS2 + q * 4])          = ba;
        *reinterpret_cast<ulonglong2*>(&tile[(tid + PBLK) * TS2 + q * 4]) = bb;
    }
    __syncthreads();
#pragma unroll
    for (int j = 0; j < 8; j++)
        if (grN[j] < N)
            gP4[(size_t)grN[j] * 8 + 4 + cc[j]] =
                *reinterpret_cast<const float4*>(&tile[rr[j] * TS2 + cc[j] * 4]);
}

// ---------------------------------------------------------------------------
// fp16 chained dot of 8 elements (one uint4 pair): 1 HMUL2 + 3 HFMA2 in fp16
// (each half-lane sums only 4 products), then 2 cvt + 1 add into fp32.
// 8 instrs per 8 elements vs 24 for convert-then-FFMA.
// ---------------------------------------------------------------------------
__device__ __forceinline__ float dot8_h(uint4 a, uint4 b)
{
    __half2 s = __hmul2(*reinterpret_cast<const __half2*>(&a.x),
                        *reinterpret_cast<const __half2*>(&b.x));
    s = __hfma2(*reinterpret_cast<const __half2*>(&a.y),
                *reinterpret_cast<const __half2*>(&b.y), s);
    s = __hfma2(*reinterpret_cast<const __half2*>(&a.z),
                *reinterpret_cast<const __half2*>(&b.z), s);
    s = __hfma2(*reinterpret_cast<const __half2*>(&a.w),
                *reinterpret_cast<const __half2*>(&b.w), s);
    float2 f = __half22float2(s);
    return f.x + f.y;
}

// ---------------------------------------------------------------------------
// Kernel 2: per-edge work, 8 lanes per edge.
// out layout: [adj_logits (E), weights (E)]
// ---------------------------------------------------------------------------
__global__ __launch_bounds__(256)
void edge_kernel(const void* __restrict__ ei_raw,   // [2,E] int64 OR int32
                 const float* __restrict__ b1,
                 const float* __restrict__ W2,
                 const float* __restrict__ b2,
                 float* __restrict__ out,
                 int E, int N)
{
    int t   = blockIdx.x * blockDim.x + threadIdx.x;
    int e   = t >> 3;
    int sub = t & 7;
    bool valid = (e < E);
    int ec = valid ? e : (E - 1);

    int row, col;
    if (g_ei_is64) {
        const long long* ei = (const long long*)ei_raw;
        row = (int)ei[ec];
        col = (int)ei[(size_t)E + ec];
    } else {
        const int* ei = (const int*)ei_raw;
        row = ei[ec];
        col = ei[(size_t)E + ec];
    }
    row = min(max(row, 0), N - 1);
    col = min(max(col, 0), N - 1);

    const uint4* zr = reinterpret_cast<const uint4*>(g_zh) + (size_t)row * 16;
    const uint4* zc = reinterpret_cast<const uint4*>(g_zh) + (size_t)col * 16;

    uint4 a0 = zr[sub],     b0 = zc[sub];
    uint4 a1 = zr[sub + 8], b1u = zc[sub + 8];
    float acc = dot8_h(a0, b0) + dot8_h(a1, b1u);

    acc += __shfl_xor_sync(0xffffffffu, acc, 1);
    acc += __shfl_xor_sync(0xffffffffu, acc, 2);
    acc += __shfl_xor_sync(0xffffffffu, acc, 4);

    // MLP: each lane covers 2 hidden units
    const float2* P2 = reinterpret_cast<const float2*>(g_P);
    float2 pr = P2[(size_t)row * 16 + sub];
    float2 pc = P2[(size_t)col * 16 + 8 + sub];
    float2 bb = reinterpret_cast<const float2*>(b1)[sub];
    float2 w2 = reinterpret_cast<const float2*>(W2)[sub];

    float h0 = fmaxf(pr.x + pc.x + bb.x, 0.f);
    float h1 = fmaxf(pr.y + pc.y + bb.y, 0.f);

    float part = h0 * w2.x + h1 * w2.y;
    part += __shfl_xor_sync(0xffffffffu, part, 1);
    part += __shfl_xor_sync(0xffffffffu, part, 2);
    part += __shfl_xor_sync(0xffffffffu, part, 4);

    if (valid && sub == 0) {
        float x = part + b2[0];
        float w = fmaxf(x, 0.f) + log1pf(expf(-fabsf(x)));
        out[e]             = acc;
        out[(size_t)E + e] = w;
    }
}

// ---------------------------------------------------------------------------
// Launch
// ---------------------------------------------------------------------------
extern "C" void kernel_launch(void* const* d_in, const int* in_sizes, int n_in,
                              void* d_out, int out_size)
{
    const float* z  = (const float*)d_in[0];        // [N,128] f32
    const void*  ei = d_in[1];                      // [2,E]   i64 or i32
    const float* W1 = (const float*)d_in[2];        // [256,16] f32
    const float* b1 = (const float*)d_in[3];        // [16]
    const float* W2 = (const float*)d_in[4];        // [16,1]
    const float* b2 = (const float*)d_in[5];        // [1]
    float*       out = (float*)d_out;

    int N = in_sizes[0] / 128;
    int E = in_sizes[1] / 2;

    int blocks1 = (N + NPB - 1) / NPB;
    proj_kernel<<<blocks1, PBLK>>>(z, W1, (const long long*)ei, N, E);

    long long threads2 = (long long)E * 8;
    int blocks2 = (int)((threads2 + 255) / 256);
    edge_kernel<<<blocks2, 256>>>(ei, b1, W2, b2, out, E, N);
}